// round 11
// baseline (speedup 1.0000x reference)
#include <cuda_runtime.h>
#include <cuda_bf16.h>
#include <cstdint>

// Warp-specialized Affine_Linear (HMMA; tcgen05 unavailable on compute_103 target).
//  10 producer warps: 2-deep LDG-pipelined frame build (loads for 2 items in flight,
//                     first two issued BEFORE the barrier/y_copy region),
//                     Y epilogue = pure linear float4 copy from consumed buffer.
//   6 consumer warps: m32n32 HMMA tiles, pipelined k-loop, scatter into Y-linear layout.
// Identical to the 68.1us round-9 kernel except the producer load pipeline depth.

#define THREADS 512
#define NPROD   320
#define NCONS   192
#define TOKBUF  32
#define NITEMS  (TOKBUF*32)    // 1024 e-pair items per group
#define APITCH  392            // halves/row (784B = 49 chunks == 1 mod 8, ldsm conflict-free)
#define BPITCH  72             // halves/row (144B = 9 chunks == 1 mod 8)
#define SB_BYTES   (384*BPITCH*2)            // 55296
#define ABUF_BYTES (96*APITCH*2)             // 75264
#define SMEM_TOTAL (SB_BYTES + 2*ABUF_BYTES) // 205824

__device__ __forceinline__ uint32_t smem_u32(const void* p) {
    return (uint32_t)__cvta_generic_to_shared(p);
}
__device__ __forceinline__ void ldsm_x4(uint32_t* r, uint32_t addr) {
    asm volatile("ldmatrix.sync.aligned.m8n8.x4.shared.b16 {%0,%1,%2,%3}, [%4];"
                 : "=r"(r[0]), "=r"(r[1]), "=r"(r[2]), "=r"(r[3]) : "r"(addr));
}
__device__ __forceinline__ void ldsm_x4_t(uint32_t* r, uint32_t addr) {
    asm volatile("ldmatrix.sync.aligned.m8n8.x4.trans.shared.b16 {%0,%1,%2,%3}, [%4];"
                 : "=r"(r[0]), "=r"(r[1]), "=r"(r[2]), "=r"(r[3]) : "r"(addr));
}
__device__ __forceinline__ void mma16816(float* c, const uint32_t* a, uint32_t b0, uint32_t b1) {
    asm volatile("mma.sync.aligned.m16n8k16.row.col.f32.bf16.bf16.f32 "
                 "{%0,%1,%2,%3}, {%4,%5,%6,%7}, {%8,%9}, {%0,%1,%2,%3};"
                 : "+f"(c[0]), "+f"(c[1]), "+f"(c[2]), "+f"(c[3])
                 : "r"(a[0]), "r"(a[1]), "r"(a[2]), "r"(a[3]), "r"(b0), "r"(b1));
}

struct Frag {
    uint32_t ah0[4], ah1[4], al0[4], al1[4];
    uint32_t bh[2][4], bl[2][4];
};

__device__ __forceinline__ void load_frags(Frag& F, uint32_t aBase, uint32_t bBase, int ks) {
    uint32_t ao = (uint32_t)(ks * 32);
    ldsm_x4(F.ah0, aBase + ao);
    ldsm_x4(F.ah1, aBase + 16 * APITCH * 2 + ao);
    ldsm_x4(F.al0, aBase + 384 + ao);
    ldsm_x4(F.al1, aBase + 16 * APITCH * 2 + 384 + ao);
    uint32_t bo = (uint32_t)(ks * 16 * BPITCH * 2);
    ldsm_x4_t(F.bh[0], bBase + bo);
    ldsm_x4_t(F.bh[1], bBase + bo + 32);
    ldsm_x4_t(F.bl[0], bBase + bo + 192 * BPITCH * 2);
    ldsm_x4_t(F.bl[1], bBase + bo + 192 * BPITCH * 2 + 32);
}

// three sweeps of 8 -> 7 independent MMAs between dependent acc updates
__device__ __forceinline__ void do_mmas(float acc[2][4][4], const Frag& F) {
#pragma unroll
    for (int q = 0; q < 2; q++)
#pragma unroll
        for (int j = 0; j < 2; j++) {
            mma16816(acc[0][2*q+j], F.ah0, F.bh[q][2*j], F.bh[q][2*j+1]);
            mma16816(acc[1][2*q+j], F.ah1, F.bh[q][2*j], F.bh[q][2*j+1]);
        }
#pragma unroll
    for (int q = 0; q < 2; q++)
#pragma unroll
        for (int j = 0; j < 2; j++) {
            mma16816(acc[0][2*q+j], F.al0, F.bh[q][2*j], F.bh[q][2*j+1]);
            mma16816(acc[1][2*q+j], F.al1, F.bh[q][2*j], F.bh[q][2*j+1]);
        }
#pragma unroll
    for (int q = 0; q < 2; q++)
#pragma unroll
        for (int j = 0; j < 2; j++) {
            mma16816(acc[0][2*q+j], F.ah0, F.bl[q][2*j], F.bl[q][2*j+1]);
            mma16816(acc[1][2*q+j], F.ah1, F.bl[q][2*j], F.bl[q][2*j+1]);
        }
}

__device__ __forceinline__ void split2p(__nv_bfloat16* hi, __nv_bfloat16* lo, float v0, float v1) {
    __nv_bfloat16 h0 = __float2bfloat16(v0);
    __nv_bfloat16 h1 = __float2bfloat16(v1);
    *(__nv_bfloat162*)hi = __halves2bfloat162(h0, h1);
    *(__nv_bfloat162*)lo = __halves2bfloat162(__float2bfloat16(v0 - __bfloat162float(h0)),
                                              __float2bfloat16(v1 - __bfloat162float(h1)));
}

__device__ __forceinline__ void frame_terms(float a1x, float a2x, float a1y, float a2y,
                                            float a1z, float a2z,
                                            float x0, float x1, float x2, float t[3][3]) {
    float s1   = fmaf(a1x, a1x, fmaf(a1y, a1y, a1z * a1z));
    float inv1 = rsqrtf(fmaxf(s1, 1e-24f));
    float b1x = a1x * inv1, b1y = a1y * inv1, b1z = a1z * inv1;

    float d  = fmaf(b1x, a2x, fmaf(b1y, a2y, b1z * a2z));
    float ux = fmaf(-d, b1x, a2x);
    float uy = fmaf(-d, b1y, a2y);
    float uz = fmaf(-d, b1z, a2z);
    float s2   = fmaf(ux, ux, fmaf(uy, uy, uz * uz));
    float inv2 = rsqrtf(fmaxf(s2, 1e-24f));
    float b2x = ux * inv2, b2y = uy * inv2, b2z = uz * inv2;

    float b3x = fmaf(b1y, b2z, -b1z * b2y);
    float b3y = fmaf(b1z, b2x, -b1x * b2z);
    float b3z = fmaf(b1x, b2y, -b1y * b2x);

    float rt0 = fmaf(b1x, x0, fmaf(b1y, x1, b1z * x2));
    float rt1 = fmaf(b2x, x0, fmaf(b2y, x1, b2z * x2));
    float rt2 = fmaf(b3x, x0, fmaf(b3y, x1, b3z * x2));

    t[0][0] = fmaf(b1x, rt0,  b2x * rt1);
    t[0][1] = fmaf(b1y, rt0,  b2y * rt1);
    t[0][2] = fmaf(b1z, rt0,  b2z * rt1);
    t[1][0] = fmaf(b2x, rt0, -b1x * rt1);
    t[1][1] = fmaf(b2y, rt0, -b1y * rt1);
    t[1][2] = fmaf(b2z, rt0, -b1z * rt1);
    t[2][0] = b3x * rt2;
    t[2][1] = b3y * rt2;
    t[2][2] = b3z * rt2;
}

struct Stage {
    float4 j0, j1, j2;
    float2 xa, xb, xc;
};

__device__ __forceinline__ Stage load_stage(const float* __restrict__ X,
                                            const float* __restrict__ J,
                                            long long tokBase, int p) {
    Stage s;
    int tok = p >> 5;
    int e0  = (p & 31) << 1;
    long long base = (tokBase + tok) * 64 + e0;
    const float4* Jp = (const float4*)(J + base * 6);
    s.j0 = Jp[0]; s.j1 = Jp[1]; s.j2 = Jp[2];
    const float2* Xp = (const float2*)(X + base * 3);
    s.xa = Xp[0]; s.xb = Xp[1]; s.xc = Xp[2];
    return s;
}

__device__ __forceinline__ void compute_store(const Stage& s, int p, __nv_bfloat16* sA) {
    int tok = p >> 5;
    int e0  = (p & 31) << 1;
    float t0[3][3], t1[3][3];
    frame_terms(s.j0.x, s.j0.y, s.j0.z, s.j0.w, s.j1.x, s.j1.y,
                s.xa.x, s.xa.y, s.xb.x, t0);
    frame_terms(s.j1.z, s.j1.w, s.j2.x, s.j2.y, s.j2.z, s.j2.w,
                s.xb.y, s.xc.x, s.xc.y, t1);
    int k0 = 3 * e0;
#pragma unroll
    for (int i = 0; i < 3; i++) {
        __nv_bfloat16* r = sA + (tok * 3 + i) * APITCH + k0;
        split2p(r + 0, r + 192 + 0, t0[0][i], t0[1][i]);
        split2p(r + 2, r + 192 + 2, t0[2][i], t1[0][i]);
        split2p(r + 4, r + 192 + 4, t1[1][i], t1[2][i]);
    }
}

__global__ __launch_bounds__(THREADS, 1)
void affine_ws7(const float* __restrict__ X,
                const float* __restrict__ J,
                const float* __restrict__ A,
                const float* __restrict__ Bm,
                const float* __restrict__ C,
                float* __restrict__ Y,
                int ngroups)
{
    extern __shared__ char smem[];
    __nv_bfloat16* sB  = (__nv_bfloat16*)smem;               // [k(384)][f(64)] pitch BPITCH
    __nv_bfloat16* sA0 = (__nv_bfloat16*)(smem + SB_BYTES);  // two buffers [96][APITCH]

    const int tid = threadIdx.x;

    // ---- weights -> sB, split hi/lo, packed bf16x2 along f ----
    for (int q = tid; q < 2048; q += THREADS) {
        int e  = q & 63;
        int f0 = (q >> 6) << 1;
        float wa0 = A[f0 * 64 + e],  wa1 = A[(f0 + 1) * 64 + e];
        float wb0 = Bm[f0 * 64 + e], wb1 = Bm[(f0 + 1) * 64 + e];
        float wc0 = C[f0 * 64 + e],  wc1 = C[(f0 + 1) * 64 + e];
        int k = e * 3;
        split2p(&sB[(k+0)*BPITCH + f0], &sB[(192+k+0)*BPITCH + f0], wa0, wa1);
        split2p(&sB[(k+1)*BPITCH + f0], &sB[(192+k+1)*BPITCH + f0], wb0, wb1);
        split2p(&sB[(k+2)*BPITCH + f0], &sB[(192+k+2)*BPITCH + f0], wc0, wc1);
    }
    __syncthreads();

    int nit = 0;
    for (int g = blockIdx.x; g < ngroups; g += gridDim.x) nit++;

    if (tid < NPROD) {
        // ================= PRODUCERS (warps 0-9) =================
        int it = 0;
        for (int g = blockIdx.x; g < ngroups; g += gridDim.x, it++) {
            int buf = it & 1;
            __nv_bfloat16* sA = sA0 + buf * (ABUF_BYTES / 2);
            long long tokBase = (long long)g * TOKBUF;

            // 2-deep prefetch: items tid and tid+NPROD issued BEFORE the barrier,
            // so their DRAM latency overlaps barrier wait + y_copy.
            Stage s0 = load_stage(X, J, tokBase, tid);
            Stage s1;
            if (tid + NPROD < NITEMS) s1 = load_stage(X, J, tokBase, tid + NPROD);

            if (it >= 2) {
                int bid = 3 + buf;   // EMPTY: consumers wrote sOutY for group it-2
                asm volatile("bar.sync %0, %1;" :: "r"(bid), "n"(THREADS) : "memory");
                // pure linear copy: sOutY (aliased in sA) -> Y
                const float4* src = (const float4*)sA;
                float4* dst = (float4*)(Y +
                    ((long long)blockIdx.x + (long long)(it - 2) * gridDim.x) * (TOKBUF * 192));
                for (int q = tid; q < (TOKBUF * 192) / 4; q += NPROD)
                    dst[q] = src[q];
                // producers must all finish reading sOutY before any overwrite
                asm volatile("bar.sync 6, %0;" :: "n"(NPROD) : "memory");
            }

            // 2-deep software-pipelined item loop
            int p = tid;
#pragma unroll 1
            while (p < NITEMS) {
                int p2 = p + 2 * NPROD;
                Stage s2;
                if (p2 < NITEMS) s2 = load_stage(X, J, tokBase, p2);
                compute_store(s0, p, sA);
                s0 = s1;
                s1 = s2;
                p += NPROD;
            }
            {
                int bid = 1 + buf;   // FULL
                asm volatile("bar.arrive %0, %1;" :: "r"(bid), "n"(THREADS) : "memory");
            }
        }
        // ---- drain: copy out the last <=2 sOutY buffers ----
#pragma unroll 1
        for (int k = 0; k < 2; k++) {
            int itd = nit + k;
            int src_it = itd - 2;
            if (src_it < 0 || src_it >= nit) continue;
            int buf = itd & 1;
            int bid = 3 + buf;
            asm volatile("bar.sync %0, %1;" :: "r"(bid), "n"(THREADS) : "memory");
            const float4* src = (const float4*)(sA0 + buf * (ABUF_BYTES / 2));
            float4* dst = (float4*)(Y +
                ((long long)blockIdx.x + (long long)src_it * gridDim.x) * (TOKBUF * 192));
            for (int q = tid; q < (TOKBUF * 192) / 4; q += NPROD)
                dst[q] = src[q];
        }
    } else {
        // ================= CONSUMERS (warps 10-15) =================
        const int cw   = (tid - NPROD) >> 5;   // 0..5
        const int lane = tid & 31;
        const int row0 = (cw >> 1) * 32;       // 3 m-tiles
        const int n0   = (cw & 1) * 32;        // 2 n-tiles
        const int gq   = lane >> 2;
        const int tq   = lane & 3;

        // loop-invariant Y-linear offsets for the 4 row variants (mt,half)
        int offY[4];
#pragma unroll
        for (int v = 0; v < 4; v++) {
            int r   = row0 + (v >> 1) * 16 + (v & 1) * 8 + gq;
            int tok = r / 3;
            offY[v] = tok * 192 + (r - 3 * tok);
        }

        const uint32_t bBase = smem_u32(sB + (lane & 15) * BPITCH + n0 + ((lane >> 4) << 3));

        int it = 0;
        for (int g = blockIdx.x; g < ngroups; g += gridDim.x, it++) {
            int buf = it & 1;
            {
                int bid = 1 + buf;   // FULL
                asm volatile("bar.sync %0, %1;" :: "r"(bid), "n"(THREADS) : "memory");
            }
            __nv_bfloat16* sA = sA0 + buf * (ABUF_BYTES / 2);
            float* sOutY = (float*)sA;

            uint32_t aBase = smem_u32(sA + (row0 + (lane & 15)) * APITCH + ((lane >> 4) << 3));

            float acc[2][4][4];
#pragma unroll
            for (int mt = 0; mt < 2; mt++)
#pragma unroll
                for (int q = 0; q < 4; q++)
#pragma unroll
                    for (int r = 0; r < 4; r++) acc[mt][q][r] = 0.f;

            // software-pipelined k-loop (12 steps, double-buffered fragments)
            Frag F[2];
            load_frags(F[0], aBase, bBase, 0);
#pragma unroll
            for (int ks = 0; ks < 12; ks++) {
                if (ks < 11) load_frags(F[(ks + 1) & 1], aBase, bBase, ks + 1);
                do_mmas(acc, F[ks & 1]);
            }

            // all consumers done reading sA before sOutY overwrite
            asm volatile("bar.sync 5, %0;" :: "n"(NCONS) : "memory");

            // scatter acc into Y-linear layout: sOutY[tok*192 + f*3 + i]
#pragma unroll
            for (int mt = 0; mt < 2; mt++) {
#pragma unroll
                for (int q = 0; q < 4; q++) {
                    int col3 = (n0 + q * 8 + tq * 2) * 3;
                    sOutY[offY[mt*2+0] + col3]     = acc[mt][q][0];
                    sOutY[offY[mt*2+0] + col3 + 3] = acc[mt][q][1];
                    sOutY[offY[mt*2+1] + col3]     = acc[mt][q][2];
                    sOutY[offY[mt*2+1] + col3 + 3] = acc[mt][q][3];
                }
            }
            {
                int bid = 3 + buf;   // EMPTY (sOutY ready for producer copy)
                asm volatile("bar.arrive %0, %1;" :: "r"(bid), "n"(THREADS) : "memory");
            }
        }
    }
}

extern "C" void kernel_launch(void* const* d_in, const int* in_sizes, int n_in,
                              void* d_out, int out_size)
{
    const float* X  = (const float*)d_in[0];
    const float* J  = (const float*)d_in[1];
    const float* A  = (const float*)d_in[2];
    const float* Bm = (const float*)d_in[3];
    const float* C  = (const float*)d_in[4];
    float* Y = (float*)d_out;

    int ntok    = in_sizes[0] / (64 * 3);   // B*N
    int ngroups = ntok / TOKBUF;            // 2048

    cudaFuncSetAttribute(affine_ws7,
                         cudaFuncAttributeMaxDynamicSharedMemorySize, SMEM_TOTAL);

    int blocks = 152;
    if (blocks > ngroups) blocks = ngroups;
    affine_ws7<<<blocks, THREADS, SMEM_TOTAL>>>(X, J, A, Bm, C, Y, ngroups);
}

// round 12
// speedup vs baseline: 1.1803x; 1.1803x over previous
#include <cuda_runtime.h>
#include <cuda_bf16.h>
#include <cstdint>

// Warp-specialized Affine_Linear (HMMA; tcgen05 unavailable on compute_103 target).
// Round-9 baseline (68.1us) + L2 prefetch of next group's inputs (zero-register
// latency hiding for the producer in-loop LDGs).
//  10 producer warps: frame build w/ 1-deep register pipeline + L2 prefetch,
//                     Y epilogue = pure linear float4 copy from consumed buffer.
//   6 consumer warps: m32n32 HMMA tiles, pipelined k-loop, scatter into Y-linear layout.

#define THREADS 512
#define NPROD   320
#define NCONS   192
#define TOKBUF  32
#define NITEMS  (TOKBUF*32)
#define APITCH  392            // halves/row (784B = 49 chunks == 1 mod 8, ldsm conflict-free)
#define BPITCH  72             // halves/row (144B = 9 chunks == 1 mod 8)
#define SB_BYTES   (384*BPITCH*2)            // 55296
#define ABUF_BYTES (96*APITCH*2)             // 75264
#define SMEM_TOTAL (SB_BYTES + 2*ABUF_BYTES) // 205824

__device__ __forceinline__ uint32_t smem_u32(const void* p) {
    return (uint32_t)__cvta_generic_to_shared(p);
}
__device__ __forceinline__ void ldsm_x4(uint32_t* r, uint32_t addr) {
    asm volatile("ldmatrix.sync.aligned.m8n8.x4.shared.b16 {%0,%1,%2,%3}, [%4];"
                 : "=r"(r[0]), "=r"(r[1]), "=r"(r[2]), "=r"(r[3]) : "r"(addr));
}
__device__ __forceinline__ void ldsm_x4_t(uint32_t* r, uint32_t addr) {
    asm volatile("ldmatrix.sync.aligned.m8n8.x4.trans.shared.b16 {%0,%1,%2,%3}, [%4];"
                 : "=r"(r[0]), "=r"(r[1]), "=r"(r[2]), "=r"(r[3]) : "r"(addr));
}
__device__ __forceinline__ void mma16816(float* c, const uint32_t* a, uint32_t b0, uint32_t b1) {
    asm volatile("mma.sync.aligned.m16n8k16.row.col.f32.bf16.bf16.f32 "
                 "{%0,%1,%2,%3}, {%4,%5,%6,%7}, {%8,%9}, {%0,%1,%2,%3};"
                 : "+f"(c[0]), "+f"(c[1]), "+f"(c[2]), "+f"(c[3])
                 : "r"(a[0]), "r"(a[1]), "r"(a[2]), "r"(a[3]), "r"(b0), "r"(b1));
}
__device__ __forceinline__ void prefetch_l2(const void* p) {
    asm volatile("prefetch.global.L2 [%0];" :: "l"(p));
}

struct Frag {
    uint32_t ah0[4], ah1[4], al0[4], al1[4];
    uint32_t bh[2][4], bl[2][4];
};

__device__ __forceinline__ void load_frags(Frag& F, uint32_t aBase, uint32_t bBase, int ks) {
    uint32_t ao = (uint32_t)(ks * 32);
    ldsm_x4(F.ah0, aBase + ao);
    ldsm_x4(F.ah1, aBase + 16 * APITCH * 2 + ao);
    ldsm_x4(F.al0, aBase + 384 + ao);
    ldsm_x4(F.al1, aBase + 16 * APITCH * 2 + 384 + ao);
    uint32_t bo = (uint32_t)(ks * 16 * BPITCH * 2);
    ldsm_x4_t(F.bh[0], bBase + bo);
    ldsm_x4_t(F.bh[1], bBase + bo + 32);
    ldsm_x4_t(F.bl[0], bBase + bo + 192 * BPITCH * 2);
    ldsm_x4_t(F.bl[1], bBase + bo + 192 * BPITCH * 2 + 32);
}

// three sweeps of 8 -> 7 independent MMAs between dependent acc updates
__device__ __forceinline__ void do_mmas(float acc[2][4][4], const Frag& F) {
#pragma unroll
    for (int q = 0; q < 2; q++)
#pragma unroll
        for (int j = 0; j < 2; j++) {
            mma16816(acc[0][2*q+j], F.ah0, F.bh[q][2*j], F.bh[q][2*j+1]);
            mma16816(acc[1][2*q+j], F.ah1, F.bh[q][2*j], F.bh[q][2*j+1]);
        }
#pragma unroll
    for (int q = 0; q < 2; q++)
#pragma unroll
        for (int j = 0; j < 2; j++) {
            mma16816(acc[0][2*q+j], F.al0, F.bh[q][2*j], F.bh[q][2*j+1]);
            mma16816(acc[1][2*q+j], F.al1, F.bh[q][2*j], F.bh[q][2*j+1]);
        }
#pragma unroll
    for (int q = 0; q < 2; q++)
#pragma unroll
        for (int j = 0; j < 2; j++) {
            mma16816(acc[0][2*q+j], F.ah0, F.bl[q][2*j], F.bl[q][2*j+1]);
            mma16816(acc[1][2*q+j], F.ah1, F.bl[q][2*j], F.bl[q][2*j+1]);
        }
}

__device__ __forceinline__ void split2p(__nv_bfloat16* hi, __nv_bfloat16* lo, float v0, float v1) {
    __nv_bfloat16 h0 = __float2bfloat16(v0);
    __nv_bfloat16 h1 = __float2bfloat16(v1);
    *(__nv_bfloat162*)hi = __halves2bfloat162(h0, h1);
    *(__nv_bfloat162*)lo = __halves2bfloat162(__float2bfloat16(v0 - __bfloat162float(h0)),
                                              __float2bfloat16(v1 - __bfloat162float(h1)));
}

__device__ __forceinline__ void frame_terms(float a1x, float a2x, float a1y, float a2y,
                                            float a1z, float a2z,
                                            float x0, float x1, float x2, float t[3][3]) {
    float s1   = fmaf(a1x, a1x, fmaf(a1y, a1y, a1z * a1z));
    float inv1 = rsqrtf(fmaxf(s1, 1e-24f));
    float b1x = a1x * inv1, b1y = a1y * inv1, b1z = a1z * inv1;

    float d  = fmaf(b1x, a2x, fmaf(b1y, a2y, b1z * a2z));
    float ux = fmaf(-d, b1x, a2x);
    float uy = fmaf(-d, b1y, a2y);
    float uz = fmaf(-d, b1z, a2z);
    float s2   = fmaf(ux, ux, fmaf(uy, uy, uz * uz));
    float inv2 = rsqrtf(fmaxf(s2, 1e-24f));
    float b2x = ux * inv2, b2y = uy * inv2, b2z = uz * inv2;

    float b3x = fmaf(b1y, b2z, -b1z * b2y);
    float b3y = fmaf(b1z, b2x, -b1x * b2z);
    float b3z = fmaf(b1x, b2y, -b1y * b2x);

    float rt0 = fmaf(b1x, x0, fmaf(b1y, x1, b1z * x2));
    float rt1 = fmaf(b2x, x0, fmaf(b2y, x1, b2z * x2));
    float rt2 = fmaf(b3x, x0, fmaf(b3y, x1, b3z * x2));

    t[0][0] = fmaf(b1x, rt0,  b2x * rt1);
    t[0][1] = fmaf(b1y, rt0,  b2y * rt1);
    t[0][2] = fmaf(b1z, rt0,  b2z * rt1);
    t[1][0] = fmaf(b2x, rt0, -b1x * rt1);
    t[1][1] = fmaf(b2y, rt0, -b1y * rt1);
    t[1][2] = fmaf(b2z, rt0, -b1z * rt1);
    t[2][0] = b3x * rt2;
    t[2][1] = b3y * rt2;
    t[2][2] = b3z * rt2;
}

struct Stage {
    float4 j0, j1, j2;
    float2 xa, xb, xc;
};

__device__ __forceinline__ Stage load_stage(const float* __restrict__ X,
                                            const float* __restrict__ J,
                                            long long tokBase, int p) {
    Stage s;
    int tok = p >> 5;
    int e0  = (p & 31) << 1;
    long long base = (tokBase + tok) * 64 + e0;
    const float4* Jp = (const float4*)(J + base * 6);
    s.j0 = Jp[0]; s.j1 = Jp[1]; s.j2 = Jp[2];
    const float2* Xp = (const float2*)(X + base * 3);
    s.xa = Xp[0]; s.xb = Xp[1]; s.xc = Xp[2];
    return s;
}

__device__ __forceinline__ void compute_store(const Stage& s, int p, __nv_bfloat16* sA) {
    int tok = p >> 5;
    int e0  = (p & 31) << 1;
    float t0[3][3], t1[3][3];
    frame_terms(s.j0.x, s.j0.y, s.j0.z, s.j0.w, s.j1.x, s.j1.y,
                s.xa.x, s.xa.y, s.xb.x, t0);
    frame_terms(s.j1.z, s.j1.w, s.j2.x, s.j2.y, s.j2.z, s.j2.w,
                s.xb.y, s.xc.x, s.xc.y, t1);
    int k0 = 3 * e0;
#pragma unroll
    for (int i = 0; i < 3; i++) {
        __nv_bfloat16* r = sA + (tok * 3 + i) * APITCH + k0;
        split2p(r + 0, r + 192 + 0, t0[0][i], t0[1][i]);
        split2p(r + 2, r + 192 + 2, t0[2][i], t1[0][i]);
        split2p(r + 4, r + 192 + 4, t1[1][i], t1[2][i]);
    }
}

__global__ __launch_bounds__(THREADS, 1)
void affine_ws8(const float* __restrict__ X,
                const float* __restrict__ J,
                const float* __restrict__ A,
                const float* __restrict__ Bm,
                const float* __restrict__ C,
                float* __restrict__ Y,
                int ngroups)
{
    extern __shared__ char smem[];
    __nv_bfloat16* sB  = (__nv_bfloat16*)smem;               // [k(384)][f(64)] pitch BPITCH
    __nv_bfloat16* sA0 = (__nv_bfloat16*)(smem + SB_BYTES);  // two buffers [96][APITCH]

    const int tid = threadIdx.x;

    // ---- weights -> sB, split hi/lo, packed bf16x2 along f ----
    for (int q = tid; q < 2048; q += THREADS) {
        int e  = q & 63;
        int f0 = (q >> 6) << 1;
        float wa0 = A[f0 * 64 + e],  wa1 = A[(f0 + 1) * 64 + e];
        float wb0 = Bm[f0 * 64 + e], wb1 = Bm[(f0 + 1) * 64 + e];
        float wc0 = C[f0 * 64 + e],  wc1 = C[(f0 + 1) * 64 + e];
        int k = e * 3;
        split2p(&sB[(k+0)*BPITCH + f0], &sB[(192+k+0)*BPITCH + f0], wa0, wa1);
        split2p(&sB[(k+1)*BPITCH + f0], &sB[(192+k+1)*BPITCH + f0], wb0, wb1);
        split2p(&sB[(k+2)*BPITCH + f0], &sB[(192+k+2)*BPITCH + f0], wc0, wc1);
    }
    __syncthreads();

    int nit = 0;
    for (int g = blockIdx.x; g < ngroups; g += gridDim.x) nit++;

    if (tid < NPROD) {
        // ================= PRODUCERS (warps 0-9) =================
        int it = 0;
        for (int g = blockIdx.x; g < ngroups; g += gridDim.x, it++) {
            int buf = it & 1;
            __nv_bfloat16* sA = sA0 + buf * (ABUF_BYTES / 2);
            long long tokBase = (long long)g * TOKBUF;

            // prefetch the first item BEFORE blocking on the EMPTY barrier
            Stage cur = load_stage(X, J, tokBase, tid);

            if (it >= 2) {
                int bid = 3 + buf;   // EMPTY: consumers wrote sOutY for group it-2
                asm volatile("bar.sync %0, %1;" :: "r"(bid), "n"(THREADS) : "memory");
                // pure linear copy: sOutY (aliased in sA) -> Y; overlaps prefetch LDG
                const float4* src = (const float4*)sA;
                float4* dst = (float4*)(Y +
                    ((long long)blockIdx.x + (long long)(it - 2) * gridDim.x) * (TOKBUF * 192));
                for (int q = tid; q < (TOKBUF * 192) / 4; q += NPROD)
                    dst[q] = src[q];
                // producers must all finish reading sOutY before any overwrite
                asm volatile("bar.sync 6, %0;" :: "n"(NPROD) : "memory");
            }

            // next group's token base for L2 prefetch (addresses this thread LDGs next it)
            const int gn = g + gridDim.x;
            const bool pf = (gn < ngroups);
            const long long tokBaseN = (long long)gn * TOKBUF;

            // software-pipelined item loop (items: tid, tid+NPROD, ...)
            int p = tid;
#pragma unroll 1
            while (p < NITEMS) {
                int pn = p + NPROD;
                Stage nxt;
                if (pn < NITEMS) nxt = load_stage(X, J, tokBase, pn);
                if (pf) {
                    // same item, next group -> warms L2 for next iteration's LDGs
                    int tok = p >> 5;
                    int e0  = (p & 31) << 1;
                    long long baseN = (tokBaseN + tok) * 64 + e0;
                    prefetch_l2(J + baseN * 6);
                    prefetch_l2(X + baseN * 3);
                }
                compute_store(cur, p, sA);
                cur = nxt;
                p = pn;
            }
            {
                int bid = 1 + buf;   // FULL
                asm volatile("bar.arrive %0, %1;" :: "r"(bid), "n"(THREADS) : "memory");
            }
        }
        // ---- drain: copy out the last <=2 sOutY buffers ----
#pragma unroll 1
        for (int k = 0; k < 2; k++) {
            int itd = nit + k;
            int src_it = itd - 2;
            if (src_it < 0 || src_it >= nit) continue;
            int buf = itd & 1;
            int bid = 3 + buf;
            asm volatile("bar.sync %0, %1;" :: "r"(bid), "n"(THREADS) : "memory");
            const float4* src = (const float4*)(sA0 + buf * (ABUF_BYTES / 2));
            float4* dst = (float4*)(Y +
                ((long long)blockIdx.x + (long long)src_it * gridDim.x) * (TOKBUF * 192));
            for (int q = tid; q < (TOKBUF * 192) / 4; q += NPROD)
                dst[q] = src[q];
        }
    } else {
        // ================= CONSUMERS (warps 10-15) =================
        const int cw   = (tid - NPROD) >> 5;   // 0..5
        const int lane = tid & 31;
        const int row0 = (cw >> 1) * 32;       // 3 m-tiles
        const int n0   = (cw & 1) * 32;        // 2 n-tiles
        const int gq   = lane >> 2;
        const int tq   = lane & 3;

        // loop-invariant Y-linear offsets for the 4 row variants (mt,half)
        int offY[4];
#pragma unroll
        for (int v = 0; v < 4; v++) {
            int r   = row0 + (v >> 1) * 16 + (v & 1) * 8 + gq;
            int tok = r / 3;
            offY[v] = tok * 192 + (r - 3 * tok);
        }

        const uint32_t bBase = smem_u32(sB + (lane & 15) * BPITCH + n0 + ((lane >> 4) << 3));

        int it = 0;
        for (int g = blockIdx.x; g < ngroups; g += gridDim.x, it++) {
            int buf = it & 1;
            {
                int bid = 1 + buf;   // FULL
                asm volatile("bar.sync %0, %1;" :: "r"(bid), "n"(THREADS) : "memory");
            }
            __nv_bfloat16* sA = sA0 + buf * (ABUF_BYTES / 2);
            float* sOutY = (float*)sA;

            uint32_t aBase = smem_u32(sA + (row0 + (lane & 15)) * APITCH + ((lane >> 4) << 3));

            float acc[2][4][4];
#pragma unroll
            for (int mt = 0; mt < 2; mt++)
#pragma unroll
                for (int q = 0; q < 4; q++)
#pragma unroll
                    for (int r = 0; r < 4; r++) acc[mt][q][r] = 0.f;

            // software-pipelined k-loop (12 steps, double-buffered fragments)
            Frag F[2];
            load_frags(F[0], aBase, bBase, 0);
#pragma unroll
            for (int ks = 0; ks < 12; ks++) {
                if (ks < 11) load_frags(F[(ks + 1) & 1], aBase, bBase, ks + 1);
                do_mmas(acc, F[ks & 1]);
            }

            // all consumers done reading sA before sOutY overwrite
            asm volatile("bar.sync 5, %0;" :: "n"(NCONS) : "memory");

            // scatter acc into Y-linear layout: sOutY[tok*192 + f*3 + i]
#pragma unroll
            for (int mt = 0; mt < 2; mt++) {
#pragma unroll
                for (int q = 0; q < 4; q++) {
                    int col3 = (n0 + q * 8 + tq * 2) * 3;
                    sOutY[offY[mt*2+0] + col3]     = acc[mt][q][0];
                    sOutY[offY[mt*2+0] + col3 + 3] = acc[mt][q][1];
                    sOutY[offY[mt*2+1] + col3]     = acc[mt][q][2];
                    sOutY[offY[mt*2+1] + col3 + 3] = acc[mt][q][3];
                }
            }
            {
                int bid = 3 + buf;   // EMPTY (sOutY ready for producer copy)
                asm volatile("bar.arrive %0, %1;" :: "r"(bid), "n"(THREADS) : "memory");
            }
        }
    }
}

extern "C" void kernel_launch(void* const* d_in, const int* in_sizes, int n_in,
                              void* d_out, int out_size)
{
    const float* X  = (const float*)d_in[0];
    const float* J  = (const float*)d_in[1];
    const float* A  = (const float*)d_in[2];
    const float* Bm = (const float*)d_in[3];
    const float* C  = (const float*)d_in[4];
    float* Y = (float*)d_out;

    int ntok    = in_sizes[0] / (64 * 3);   // B*N
    int ngroups = ntok / TOKBUF;            // 2048

    cudaFuncSetAttribute(affine_ws8,
                         cudaFuncAttributeMaxDynamicSharedMemorySize, SMEM_TOTAL);

    int blocks = 152;
    if (blocks > ngroups) blocks = ngroups;
    affine_ws8<<<blocks, THREADS, SMEM_TOTAL>>>(X, J, A, Bm, C, Y, ngroups);
}

// round 13
// speedup vs baseline: 1.1892x; 1.0075x over previous
#include <cuda_runtime.h>
#include <cuda_bf16.h>
#include <cstdint>

// Warp-specialized Affine_Linear (HMMA; tcgen05 unavailable on compute_103 target).
// Round-12 base (64.3us: L2 prefetch) + sub-tile FULL barriers:
// producers arrive FULL_k after finishing item k+1 (tokens 0..10(k+2)-1 complete),
// consumer m-tile k starts its k-loop as soon as its rows are ready.
//  barriers: 1..6 = FULLsub(buf,mtile) cnt384 ; 7,8 = EMPTY(buf) cnt512 ;
//            9 = consumer-internal cnt192 ; 10 = producer-internal cnt320

#define THREADS 512
#define NPROD   320
#define NCONS   192
#define TOKBUF  32
#define NITEMS  (TOKBUF*32)
#define APITCH  392            // halves/row (784B = 49 chunks == 1 mod 8, ldsm conflict-free)
#define BPITCH  72             // halves/row (144B = 9 chunks == 1 mod 8)
#define SB_BYTES   (384*BPITCH*2)            // 55296
#define ABUF_BYTES (96*APITCH*2)             // 75264
#define SMEM_TOTAL (SB_BYTES + 2*ABUF_BYTES) // 205824

__device__ __forceinline__ uint32_t smem_u32(const void* p) {
    return (uint32_t)__cvta_generic_to_shared(p);
}
__device__ __forceinline__ void ldsm_x4(uint32_t* r, uint32_t addr) {
    asm volatile("ldmatrix.sync.aligned.m8n8.x4.shared.b16 {%0,%1,%2,%3}, [%4];"
                 : "=r"(r[0]), "=r"(r[1]), "=r"(r[2]), "=r"(r[3]) : "r"(addr));
}
__device__ __forceinline__ void ldsm_x4_t(uint32_t* r, uint32_t addr) {
    asm volatile("ldmatrix.sync.aligned.m8n8.x4.trans.shared.b16 {%0,%1,%2,%3}, [%4];"
                 : "=r"(r[0]), "=r"(r[1]), "=r"(r[2]), "=r"(r[3]) : "r"(addr));
}
__device__ __forceinline__ void mma16816(float* c, const uint32_t* a, uint32_t b0, uint32_t b1) {
    asm volatile("mma.sync.aligned.m16n8k16.row.col.f32.bf16.bf16.f32 "
                 "{%0,%1,%2,%3}, {%4,%5,%6,%7}, {%8,%9}, {%0,%1,%2,%3};"
                 : "+f"(c[0]), "+f"(c[1]), "+f"(c[2]), "+f"(c[3])
                 : "r"(a[0]), "r"(a[1]), "r"(a[2]), "r"(a[3]), "r"(b0), "r"(b1));
}
__device__ __forceinline__ void prefetch_l2(const void* p) {
    asm volatile("prefetch.global.L2 [%0];" :: "l"(p));
}

struct Frag {
    uint32_t ah0[4], ah1[4], al0[4], al1[4];
    uint32_t bh[2][4], bl[2][4];
};

__device__ __forceinline__ void load_frags(Frag& F, uint32_t aBase, uint32_t bBase, int ks) {
    uint32_t ao = (uint32_t)(ks * 32);
    ldsm_x4(F.ah0, aBase + ao);
    ldsm_x4(F.ah1, aBase + 16 * APITCH * 2 + ao);
    ldsm_x4(F.al0, aBase + 384 + ao);
    ldsm_x4(F.al1, aBase + 16 * APITCH * 2 + 384 + ao);
    uint32_t bo = (uint32_t)(ks * 16 * BPITCH * 2);
    ldsm_x4_t(F.bh[0], bBase + bo);
    ldsm_x4_t(F.bh[1], bBase + bo + 32);
    ldsm_x4_t(F.bl[0], bBase + bo + 192 * BPITCH * 2);
    ldsm_x4_t(F.bl[1], bBase + bo + 192 * BPITCH * 2 + 32);
}

// three sweeps of 8 -> 7 independent MMAs between dependent acc updates
__device__ __forceinline__ void do_mmas(float acc[2][4][4], const Frag& F) {
#pragma unroll
    for (int q = 0; q < 2; q++)
#pragma unroll
        for (int j = 0; j < 2; j++) {
            mma16816(acc[0][2*q+j], F.ah0, F.bh[q][2*j], F.bh[q][2*j+1]);
            mma16816(acc[1][2*q+j], F.ah1, F.bh[q][2*j], F.bh[q][2*j+1]);
        }
#pragma unroll
    for (int q = 0; q < 2; q++)
#pragma unroll
        for (int j = 0; j < 2; j++) {
            mma16816(acc[0][2*q+j], F.al0, F.bh[q][2*j], F.bh[q][2*j+1]);
            mma16816(acc[1][2*q+j], F.al1, F.bh[q][2*j], F.bh[q][2*j+1]);
        }
#pragma unroll
    for (int q = 0; q < 2; q++)
#pragma unroll
        for (int j = 0; j < 2; j++) {
            mma16816(acc[0][2*q+j], F.ah0, F.bl[q][2*j], F.bl[q][2*j+1]);
            mma16816(acc[1][2*q+j], F.ah1, F.bl[q][2*j], F.bl[q][2*j+1]);
        }
}

__device__ __forceinline__ void split2p(__nv_bfloat16* hi, __nv_bfloat16* lo, float v0, float v1) {
    __nv_bfloat16 h0 = __float2bfloat16(v0);
    __nv_bfloat16 h1 = __float2bfloat16(v1);
    *(__nv_bfloat162*)hi = __halves2bfloat162(h0, h1);
    *(__nv_bfloat162*)lo = __halves2bfloat162(__float2bfloat16(v0 - __bfloat162float(h0)),
                                              __float2bfloat16(v1 - __bfloat162float(h1)));
}

__device__ __forceinline__ void frame_terms(float a1x, float a2x, float a1y, float a2y,
                                            float a1z, float a2z,
                                            float x0, float x1, float x2, float t[3][3]) {
    float s1   = fmaf(a1x, a1x, fmaf(a1y, a1y, a1z * a1z));
    float inv1 = rsqrtf(fmaxf(s1, 1e-24f));
    float b1x = a1x * inv1, b1y = a1y * inv1, b1z = a1z * inv1;

    float d  = fmaf(b1x, a2x, fmaf(b1y, a2y, b1z * a2z));
    float ux = fmaf(-d, b1x, a2x);
    float uy = fmaf(-d, b1y, a2y);
    float uz = fmaf(-d, b1z, a2z);
    float s2   = fmaf(ux, ux, fmaf(uy, uy, uz * uz));
    float inv2 = rsqrtf(fmaxf(s2, 1e-24f));
    float b2x = ux * inv2, b2y = uy * inv2, b2z = uz * inv2;

    float b3x = fmaf(b1y, b2z, -b1z * b2y);
    float b3y = fmaf(b1z, b2x, -b1x * b2z);
    float b3z = fmaf(b1x, b2y, -b1y * b2x);

    float rt0 = fmaf(b1x, x0, fmaf(b1y, x1, b1z * x2));
    float rt1 = fmaf(b2x, x0, fmaf(b2y, x1, b2z * x2));
    float rt2 = fmaf(b3x, x0, fmaf(b3y, x1, b3z * x2));

    t[0][0] = fmaf(b1x, rt0,  b2x * rt1);
    t[0][1] = fmaf(b1y, rt0,  b2y * rt1);
    t[0][2] = fmaf(b1z, rt0,  b2z * rt1);
    t[1][0] = fmaf(b2x, rt0, -b1x * rt1);
    t[1][1] = fmaf(b2y, rt0, -b1y * rt1);
    t[1][2] = fmaf(b2z, rt0, -b1z * rt1);
    t[2][0] = b3x * rt2;
    t[2][1] = b3y * rt2;
    t[2][2] = b3z * rt2;
}

struct Stage {
    float4 j0, j1, j2;
    float2 xa, xb, xc;
};

__device__ __forceinline__ Stage load_stage(const float* __restrict__ X,
                                            const float* __restrict__ J,
                                            long long tokBase, int p) {
    Stage s;
    int tok = p >> 5;
    int e0  = (p & 31) << 1;
    long long base = (tokBase + tok) * 64 + e0;
    const float4* Jp = (const float4*)(J + base * 6);
    s.j0 = Jp[0]; s.j1 = Jp[1]; s.j2 = Jp[2];
    const float2* Xp = (const float2*)(X + base * 3);
    s.xa = Xp[0]; s.xb = Xp[1]; s.xc = Xp[2];
    return s;
}

__device__ __forceinline__ void pf_item(const float* __restrict__ X,
                                        const float* __restrict__ J,
                                        long long tokBaseN, int p) {
    int tok = p >> 5;
    int e0  = (p & 31) << 1;
    long long base = (tokBaseN + tok) * 64 + e0;
    prefetch_l2(J + base * 6);
    prefetch_l2(X + base * 3);
}

__device__ __forceinline__ void compute_store(const Stage& s, int p, __nv_bfloat16* sA) {
    int tok = p >> 5;
    int e0  = (p & 31) << 1;
    float t0[3][3], t1[3][3];
    frame_terms(s.j0.x, s.j0.y, s.j0.z, s.j0.w, s.j1.x, s.j1.y,
                s.xa.x, s.xa.y, s.xb.x, t0);
    frame_terms(s.j1.z, s.j1.w, s.j2.x, s.j2.y, s.j2.z, s.j2.w,
                s.xb.y, s.xc.x, s.xc.y, t1);
    int k0 = 3 * e0;
#pragma unroll
    for (int i = 0; i < 3; i++) {
        __nv_bfloat16* r = sA + (tok * 3 + i) * APITCH + k0;
        split2p(r + 0, r + 192 + 0, t0[0][i], t0[1][i]);
        split2p(r + 2, r + 192 + 2, t0[2][i], t1[0][i]);
        split2p(r + 4, r + 192 + 4, t1[1][i], t1[2][i]);
    }
}

__global__ __launch_bounds__(THREADS, 1)
void affine_ws9(const float* __restrict__ X,
                const float* __restrict__ J,
                const float* __restrict__ A,
                const float* __restrict__ Bm,
                const float* __restrict__ C,
                float* __restrict__ Y,
                int ngroups)
{
    extern __shared__ char smem[];
    __nv_bfloat16* sB  = (__nv_bfloat16*)smem;               // [k(384)][f(64)] pitch BPITCH
    __nv_bfloat16* sA0 = (__nv_bfloat16*)(smem + SB_BYTES);  // two buffers [96][APITCH]

    const int tid = threadIdx.x;

    // ---- weights -> sB, split hi/lo, packed bf16x2 along f ----
    for (int q = tid; q < 2048; q += THREADS) {
        int e  = q & 63;
        int f0 = (q >> 6) << 1;
        float wa0 = A[f0 * 64 + e],  wa1 = A[(f0 + 1) * 64 + e];
        float wb0 = Bm[f0 * 64 + e], wb1 = Bm[(f0 + 1) * 64 + e];
        float wc0 = C[f0 * 64 + e],  wc1 = C[(f0 + 1) * 64 + e];
        int k = e * 3;
        split2p(&sB[(k+0)*BPITCH + f0], &sB[(192+k+0)*BPITCH + f0], wa0, wa1);
        split2p(&sB[(k+1)*BPITCH + f0], &sB[(192+k+1)*BPITCH + f0], wb0, wb1);
        split2p(&sB[(k+2)*BPITCH + f0], &sB[(192+k+2)*BPITCH + f0], wc0, wc1);
    }
    __syncthreads();

    int nit = 0;
    for (int g = blockIdx.x; g < ngroups; g += gridDim.x) nit++;

    if (tid < NPROD) {
        // ================= PRODUCERS (warps 0-9) =================
        int it = 0;
        for (int g = blockIdx.x; g < ngroups; g += gridDim.x, it++) {
            int buf = it & 1;
            __nv_bfloat16* sA = sA0 + buf * (ABUF_BYTES / 2);
            long long tokBase = (long long)g * TOKBUF;

            // prefetch the first item BEFORE blocking on the EMPTY barrier
            Stage s0 = load_stage(X, J, tokBase, tid);

            if (it >= 2) {
                int bid = 7 + buf;   // EMPTY: consumers wrote sOutY for group it-2
                asm volatile("bar.sync %0, %1;" :: "r"(bid), "n"(THREADS) : "memory");
                // pure linear copy: sOutY (aliased in sA) -> Y; overlaps prefetch LDG
                const float4* src = (const float4*)sA;
                float4* dst = (float4*)(Y +
                    ((long long)blockIdx.x + (long long)(it - 2) * gridDim.x) * (TOKBUF * 192));
                for (int q = tid; q < (TOKBUF * 192) / 4; q += NPROD)
                    dst[q] = src[q];
                // producers must all finish reading sOutY before any overwrite
                asm volatile("bar.sync 10, %0;" :: "n"(NPROD) : "memory");
            }

            const int gn = g + gridDim.x;
            const bool pf = (gn < ngroups);
            const long long tokBaseN = (long long)gn * TOKBUF;
            const int fb = 1 + buf * 3;   // FULLsub barrier base id
            const bool has3 = (tid + 3 * NPROD) < NITEMS;   // tid < 64

            // explicitly unrolled, 1-deep pipelined item sequence (max 2 stages live)
            Stage s1 = load_stage(X, J, tokBase, tid + NPROD);
            if (pf) pf_item(X, J, tokBaseN, tid);
            compute_store(s0, tid, sA);                       // item 0 (toks 0-9)

            Stage s2 = load_stage(X, J, tokBase, tid + 2 * NPROD);
            if (pf) pf_item(X, J, tokBaseN, tid + NPROD);
            compute_store(s1, tid + NPROD, sA);               // item 1 (toks 10-19)
            asm volatile("bar.arrive %0, %1;" :: "r"(fb), "n"(384) : "memory");     // FULL m-tile 0

            Stage s3;
            if (has3) s3 = load_stage(X, J, tokBase, tid + 3 * NPROD);
            if (pf) pf_item(X, J, tokBaseN, tid + 2 * NPROD);
            compute_store(s2, tid + 2 * NPROD, sA);           // item 2 (toks 20-29)
            asm volatile("bar.arrive %0, %1;" :: "r"(fb + 1), "n"(384) : "memory"); // FULL m-tile 1

            if (has3) {
                if (pf) pf_item(X, J, tokBaseN, tid + 3 * NPROD);
                compute_store(s3, tid + 3 * NPROD, sA);       // item 3 (toks 30-31)
            }
            asm volatile("bar.arrive %0, %1;" :: "r"(fb + 2), "n"(384) : "memory"); // FULL m-tile 2
        }
        // ---- drain: copy out the last <=2 sOutY buffers ----
#pragma unroll 1
        for (int k = 0; k < 2; k++) {
            int itd = nit + k;
            int src_it = itd - 2;
            if (src_it < 0 || src_it >= nit) continue;
            int buf = itd & 1;
            int bid = 7 + buf;
            asm volatile("bar.sync %0, %1;" :: "r"(bid), "n"(THREADS) : "memory");
            const float4* src = (const float4*)(sA0 + buf * (ABUF_BYTES / 2));
            float4* dst = (float4*)(Y +
                ((long long)blockIdx.x + (long long)src_it * gridDim.x) * (TOKBUF * 192));
            for (int q = tid; q < (TOKBUF * 192) / 4; q += NPROD)
                dst[q] = src[q];
        }
    } else {
        // ================= CONSUMERS (warps 10-15) =================
        const int cw   = (tid - NPROD) >> 5;   // 0..5
        const int lane = tid & 31;
        const int mt0  = cw >> 1;              // m-tile index 0..2
        const int row0 = mt0 * 32;
        const int n0   = (cw & 1) * 32;
        const int gq   = lane >> 2;
        const int tq   = lane & 3;

        // loop-invariant Y-linear offsets for the 4 row variants (mt,half)
        int offY[4];
#pragma unroll
        for (int v = 0; v < 4; v++) {
            int r   = row0 + (v >> 1) * 16 + (v & 1) * 8 + gq;
            int tok = r / 3;
            offY[v] = tok * 192 + (r - 3 * tok);
        }

        const uint32_t bBase = smem_u32(sB + (lane & 15) * BPITCH + n0 + ((lane >> 4) << 3));

        int it = 0;
        for (int g = blockIdx.x; g < ngroups; g += gridDim.x, it++) {
            int buf = it & 1;
            {
                int bid = 1 + buf * 3 + mt0;   // FULLsub for this m-tile
                asm volatile("bar.sync %0, %1;" :: "r"(bid), "n"(384) : "memory");
            }
            __nv_bfloat16* sA = sA0 + buf * (ABUF_BYTES / 2);
            float* sOutY = (float*)sA;

            uint32_t aBase = smem_u32(sA + (row0 + (lane & 15)) * APITCH + ((lane >> 4) << 3));

            float acc[2][4][4];
#pragma unroll
            for (int mt = 0; mt < 2; mt++)
#pragma unroll
                for (int q = 0; q < 4; q++)
#pragma unroll
                    for (int r = 0; r < 4; r++) acc[mt][q][r] = 0.f;

            // software-pipelined k-loop (12 steps, double-buffered fragments)
            Frag F[2];
            load_frags(F[0], aBase, bBase, 0);
#pragma unroll
            for (int ks = 0; ks < 12; ks++) {
                if (ks < 11) load_frags(F[(ks + 1) & 1], aBase, bBase, ks + 1);
                do_mmas(acc, F[ks & 1]);
            }

            // all consumers done reading sA before sOutY overwrite
            asm volatile("bar.sync 9, %0;" :: "n"(NCONS) : "memory");

            // scatter acc into Y-linear layout: sOutY[tok*192 + f*3 + i]
#pragma unroll
            for (int mt = 0; mt < 2; mt++) {
#pragma unroll
                for (int q = 0; q < 4; q++) {
                    int col3 = (n0 + q * 8 + tq * 2) * 3;
                    sOutY[offY[mt*2+0] + col3]     = acc[mt][q][0];
                    sOutY[offY[mt*2+0] + col3 + 3] = acc[mt][q][1];
                    sOutY[offY[mt*2+1] + col3]     = acc[mt][q][2];
                    sOutY[offY[mt*2+1] + col3 + 3] = acc[mt][q][3];
                }
            }
            {
                int bid = 7 + buf;   // EMPTY (sOutY ready for producer copy)
                asm volatile("bar.arrive %0, %1;" :: "r"(bid), "n"(THREADS) : "memory");
            }
        }
    }
}

extern "C" void kernel_launch(void* const* d_in, const int* in_sizes, int n_in,
                              void* d_out, int out_size)
{
    const float* X  = (const float*)d_in[0];
    const float* J  = (const float*)d_in[1];
    const float* A  = (const float*)d_in[2];
    const float* Bm = (const float*)d_in[3];
    const float* C  = (const float*)d_in[4];
    float* Y = (float*)d_out;

    int ntok    = in_sizes[0] / (64 * 3);   // B*N
    int ngroups = ntok / TOKBUF;            // 2048

    cudaFuncSetAttribute(affine_ws9,
                         cudaFuncAttributeMaxDynamicSharedMemorySize, SMEM_TOTAL);

    int blocks = 152;
    if (blocks > ngroups) blocks = ngroups;
    affine_ws9<<<blocks, THREADS, SMEM_TOTAL>>>(X, J, A, Bm, C, Y, ngroups);
}